// round 2
// baseline (speedup 1.0000x reference)
#include <cuda_runtime.h>
#include <math.h>

#define NC     124
#define CH     64
#define IN_HW  120
#define OUT_HW 480
#define NPIX   (OUT_HW * OUT_HW)   // 230400
#define NSP    (IN_HW * IN_HW)     // 14400
#define EPSV   1e-8f

// ---------------- scratch (static __device__, no allocations) ----------------
__device__ __align__(256) float g_featsT[NSP * CH];   // (sp, ch) channel-contiguous
__device__ int g_hist[NC];
__device__ int g_off[NC + 1];
__device__ int g_pos[NC * 64];                        // 256B stride per counter
__device__ int g_sorted[NPIX];

// ---------------- K1: transpose feats (64, 14400) -> (14400, 64) -------------
__global__ __launch_bounds__(256) void k_transpose(const float* __restrict__ feats) {
    __shared__ float tile[32][33];
    const int spT = blockIdx.x * 32;   // 450 tiles over 14400
    const int chT = blockIdx.y * 32;   // 2 tiles over 64
    const int tx = threadIdx.x, ty = threadIdx.y;   // (32, 8)

    // zero histogram (done once; hist kernel runs after this in stream order)
    if (blockIdx.x == 0 && blockIdx.y == 0) {
        int t = ty * 32 + tx;
        if (t < NC) g_hist[t] = 0;
    }

#pragma unroll
    for (int k = 0; k < 32; k += 8)
        tile[ty + k][tx] = feats[(chT + ty + k) * NSP + spT + tx];
    __syncthreads();
#pragma unroll
    for (int k = 0; k < 32; k += 8)
        g_featsT[(spT + ty + k) * CH + chT + tx] = tile[tx][ty + k];
}

// ---------------- K2: class histogram ----------------------------------------
__global__ __launch_bounds__(256) void k_hist(const int* __restrict__ seg) {
    __shared__ int sh[NC];
    const int t = threadIdx.x;
    if (t < NC) sh[t] = 0;
    __syncthreads();
    for (int i = blockIdx.x * blockDim.x + t; i < NPIX; i += gridDim.x * blockDim.x)
        atomicAdd(&sh[seg[i]], 1);
    __syncthreads();
    if (t < NC) atomicAdd(&g_hist[t], sh[t]);
}

// ---------------- K3: exclusive scan (1 block) --------------------------------
__global__ __launch_bounds__(128) void k_scan() {
    __shared__ int sh[128];
    const int t = threadIdx.x;
    sh[t] = (t < NC) ? g_hist[t] : 0;
#pragma unroll
    for (int off = 1; off < 128; off <<= 1) {
        __syncthreads();
        int v = (t >= off) ? sh[t - off] : 0;
        __syncthreads();
        sh[t] += v;
    }
    __syncthreads();
    int excl = (t > 0) ? sh[t - 1] : 0;
    if (t < NC) { g_off[t] = excl; g_pos[t * 64] = excl; }
    if (t == NC) g_off[NC] = sh[NC - 1];
}

// ---------------- K4: scatter pixel indices into class-sorted order -----------
__global__ __launch_bounds__(256) void k_scatter(const int* __restrict__ seg) {
    for (int i = blockIdx.x * blockDim.x + threadIdx.x; i < NPIX;
         i += gridDim.x * blockDim.x) {
        int c = seg[i];
        int p = atomicAdd(&g_pos[c * 64], 1);
        g_sorted[p] = i;
    }
}

// ---------------- K5: main per-class reduction ---------------------------------
__device__ __forceinline__ void gather_pix(int idx, int ch, float& xv0, float& xv1) {
    int oy = idx / OUT_HW;
    int ox = idx - oy * OUT_HW;
    float fy = 0.25f * (float)oy - 0.375f;
    float fx = 0.25f * (float)ox - 0.375f;
    int by = (int)floorf(fy), bx = (int)floorf(fx);
    float wy1 = fy - (float)by, wx1 = fx - (float)bx;
    float wy0 = 1.0f - wy1, wx0 = 1.0f - wx1;
    int y0 = max(by, 0), y1 = min(by + 1, IN_HW - 1);
    int x0 = max(bx, 0), x1 = min(bx + 1, IN_HW - 1);
    const float2 a = *(const float2*)(g_featsT + (((y0 * IN_HW) + x0) << 6) + ch);
    const float2 b = *(const float2*)(g_featsT + (((y0 * IN_HW) + x1) << 6) + ch);
    const float2 c = *(const float2*)(g_featsT + (((y1 * IN_HW) + x0) << 6) + ch);
    const float2 d = *(const float2*)(g_featsT + (((y1 * IN_HW) + x1) << 6) + ch);
    xv0 = wy0 * (wx0 * a.x + wx1 * b.x) + wy1 * (wx0 * c.x + wx1 * d.x);
    xv1 = wy0 * (wx0 * a.y + wx1 * b.y) + wy1 * (wx0 * c.y + wx1 * d.y);
}

__global__ __launch_bounds__(512) void k_main(const float* __restrict__ memory,
                                              float* __restrict__ out) {
    const int c = blockIdx.x;
    const int tid = threadIdx.x;
    const int lane = tid & 31;
    const int wid = tid >> 5;
    constexpr int NW = 16;

    __shared__ float s_mem[CH], s_mn[CH];
    __shared__ float r_sum[NW][CH], r_w[NW][CH], r_s[NW];
    __shared__ float s_n2;

    if (tid < CH) s_mem[tid] = memory[c * CH + tid];
    __syncthreads();
    if (wid == 0) {
        float a = s_mem[lane], b = s_mem[lane + 32];
        float n2 = a * a + b * b;
#pragma unroll
        for (int m = 16; m; m >>= 1) n2 += __shfl_xor_sync(0xffffffffu, n2, m);
        if (lane == 0) s_n2 = n2;
    }
    __syncthreads();
    const float mn2 = s_n2;
    const float minv = 1.0f / fmaxf(sqrtf(mn2), EPSV);
    if (tid < CH) s_mn[tid] = s_mem[tid] * minv;
    __syncthreads();

    const int start = g_off[c];
    const int end = g_off[c + 1];
    const int ch = lane * 2;
    const float mn0 = s_mn[ch], mn1 = s_mn[ch + 1];

    float as0 = 0.f, as1 = 0.f, aw0 = 0.f, aw1 = 0.f, ss = 0.f;

    int p = start + wid;
    for (; p + NW < end; p += 2 * NW) {
        int ia = g_sorted[p];
        int ib = g_sorted[p + NW];
        float xa0, xa1, xb0, xb1;
        gather_pix(ia, ch, xa0, xa1);
        gather_pix(ib, ch, xb0, xb1);
        float da = xa0 * mn0 + xa1 * mn1, na = xa0 * xa0 + xa1 * xa1;
        float db = xb0 * mn0 + xb1 * mn1, nb = xb0 * xb0 + xb1 * xb1;
#pragma unroll
        for (int m = 16; m; m >>= 1) {
            da += __shfl_xor_sync(0xffffffffu, da, m);
            na += __shfl_xor_sync(0xffffffffu, na, m);
            db += __shfl_xor_sync(0xffffffffu, db, m);
            nb += __shfl_xor_sync(0xffffffffu, nb, m);
        }
        float sa = 1.0f - da / fmaxf(sqrtf(na), EPSV);
        float sb = 1.0f - db / fmaxf(sqrtf(nb), EPSV);
        as0 += xa0; as1 += xa1; as0 += xb0; as1 += xb1;
        aw0 = fmaf(sa, xa0, aw0); aw1 = fmaf(sa, xa1, aw1);
        aw0 = fmaf(sb, xb0, aw0); aw1 = fmaf(sb, xb1, aw1);
        ss += sa; ss += sb;
    }
    if (p < end) {
        int ia = g_sorted[p];
        float xa0, xa1;
        gather_pix(ia, ch, xa0, xa1);
        float da = xa0 * mn0 + xa1 * mn1, na = xa0 * xa0 + xa1 * xa1;
#pragma unroll
        for (int m = 16; m; m >>= 1) {
            da += __shfl_xor_sync(0xffffffffu, da, m);
            na += __shfl_xor_sync(0xffffffffu, na, m);
        }
        float sa = 1.0f - da / fmaxf(sqrtf(na), EPSV);
        as0 += xa0; as1 += xa1;
        aw0 = fmaf(sa, xa0, aw0); aw1 = fmaf(sa, xa1, aw1);
        ss += sa;
    }

    r_sum[wid][ch] = as0; r_sum[wid][ch + 1] = as1;
    r_w[wid][ch]   = aw0; r_w[wid][ch + 1]   = aw1;
    if (lane == 0) r_s[wid] = ss;
    __syncthreads();

    if (tid < CH) {
        float ts = 0.f, tw = 0.f, tss = 0.f;
#pragma unroll
        for (int w = 0; w < NW; w++) { ts += r_sum[w][tid]; tw += r_w[w][tid]; }
#pragma unroll
        for (int w = 0; w < NW; w++) tss += r_s[w];
        const int cnt = end - start;
        const float m = s_mem[tid];
        float outv;
        if (cnt == 0) {
            outv = m;                                   // class absent: keep memory
        } else if (mn2 == 0.0f) {
            outv = ts / fmaxf((float)cnt, 1.0f);        // zero memory row: class mean
        } else {
            float denom = (tss != 0.0f) ? tss : 1.0f;
            outv = 0.9f * m + 0.1f * (tw / denom);      // momentum update
        }
        out[c * CH + tid] = outv;
    }
}

// ---------------- launch -------------------------------------------------------
extern "C" void kernel_launch(void* const* d_in, const int* in_sizes, int n_in,
                              void* d_out, int out_size) {
    const float* feats  = (const float*)d_in[0];   // (1,64,120,120)
    const float* memory = (const float*)d_in[1];   // (124,1,64)
    const int*   seg    = (const int*)d_in[2];     // (1,480,480)
    float* out = (float*)d_out;                    // (124,1,64)

    k_transpose<<<dim3(450, 2), dim3(32, 8)>>>(feats);
    k_hist<<<148, 256>>>(seg);
    k_scan<<<1, 128>>>();
    k_scatter<<<148, 256>>>(seg);
    k_main<<<NC, 512>>>(memory, out);
}

// round 3
// speedup vs baseline: 1.1936x; 1.1936x over previous
#include <cuda_runtime.h>
#include <math.h>

#define NC     124
#define CPAD   128
#define CH     64
#define IN_HW  120
#define OUT_HW 480
#define NPIX   (OUT_HW * OUT_HW)   // 230400
#define NTAP   (IN_HW * IN_HW)     // 14400
#define EPSV   1e-8f

// ---------------- static device scratch (no allocations) ----------------
__device__ __align__(16) float g_featsT[NTAP * CH];   // (tap, ch) contiguous 256B rows
__device__ __align__(16) float g_mn[NC * CH];         // normalized memory rows
__device__ int   g_iszero[NC];
__device__ __align__(16) float g_gram[NTAP * 8];      // per tap: S,H,V,D,AD,pad3
__device__ __align__(16) float g_G[NTAP * CPAD];      // f_t . mn_c
__device__ __align__(16) float g_A[NTAP * CPAD];      // sum s_i*w_it  (by class)
__device__ __align__(16) float g_B[NTAP * CPAD];      // sum w_it
__device__ float g_acc[NC * CH];                       // selected GEMM result per class
__device__ float g_sa[CPAD];                           // sum s per class
__device__ float g_sb[CPAD];                           // count per class (as float)

// ---------------- K1: transpose feats + zero accumulators ----------------
__global__ __launch_bounds__(256) void k_init(const float* __restrict__ feats) {
    __shared__ float tile[32][33];
    const int bid = blockIdx.x;                 // 0..899
    const int tid = threadIdx.x;
    const int tx = tid & 31, ty = tid >> 5;
    const int spT = (bid % 450) * 32;
    const int chT = (bid / 450) * 32;           // 0 or 32

#pragma unroll
    for (int k = 0; k < 32; k += 8)
        tile[ty + k][tx] = feats[(chT + ty + k) * NTAP + spT + tx];
    __syncthreads();
#pragma unroll
    for (int k = 0; k < 32; k += 8)
        g_featsT[(spT + ty + k) * CH + chT + tx] = tile[tx][ty + k];

    // zero A,B (1,843,200 floats each = 230400 threads * 8)
    const int gid = bid * 256 + tid;
    float4 z = make_float4(0.f, 0.f, 0.f, 0.f);
    ((float4*)g_A)[gid * 2]     = z;
    ((float4*)g_A)[gid * 2 + 1] = z;
    ((float4*)g_B)[gid * 2]     = z;
    ((float4*)g_B)[gid * 2 + 1] = z;
    if (gid < NC * CH) g_acc[gid] = 0.f;
    if (gid < CPAD) { g_sa[gid] = 0.f; g_sb[gid] = 0.f; }
}

// ---------------- K2: normalize memory rows + is_zero flags ----------------
__global__ __launch_bounds__(64) void k_prep(const float* __restrict__ memory) {
    const int c = blockIdx.x, t = threadIdx.x;
    __shared__ float sh[64];
    __shared__ int   shz[64];
    float v = memory[c * CH + t];
    sh[t]  = v * v;
    shz[t] = (v == 0.0f) ? 1 : 0;
    __syncthreads();
    for (int o = 32; o > 0; o >>= 1) {
        if (t < o) { sh[t] += sh[t + o]; shz[t] &= shz[t + o]; }
        __syncthreads();
    }
    const float inv = 1.0f / fmaxf(sqrtf(sh[0]), EPSV);
    g_mn[c * CH + t] = v * inv;
    if (t == 0) g_iszero[c] = shz[0];
}

// ---------------- K3: neighbor Gram arrays (warp per tap) ----------------
__global__ __launch_bounds__(1024) void k_gram() {
    const int t = blockIdx.x * 32 + (threadIdx.x >> 5);
    const int lane = threadIdx.x & 31;
    const int y = t / IN_HW, x = t - y * IN_HW;
    const int xp = min(x + 1, IN_HW - 1), yp = min(y + 1, IN_HW - 1);
    const float2 a = *(const float2*)&g_featsT[(y  * IN_HW + x ) * CH + lane * 2];
    const float2 b = *(const float2*)&g_featsT[(y  * IN_HW + xp) * CH + lane * 2];
    const float2 c = *(const float2*)&g_featsT[(yp * IN_HW + x ) * CH + lane * 2];
    const float2 d = *(const float2*)&g_featsT[(yp * IN_HW + xp) * CH + lane * 2];
    float s  = a.x * a.x + a.y * a.y;
    float h  = a.x * b.x + a.y * b.y;
    float vv = a.x * c.x + a.y * c.y;
    float dd = a.x * d.x + a.y * d.y;
    float ad = b.x * c.x + b.y * c.y;
#pragma unroll
    for (int m = 16; m; m >>= 1) {
        s  += __shfl_xor_sync(0xffffffffu, s,  m);
        h  += __shfl_xor_sync(0xffffffffu, h,  m);
        vv += __shfl_xor_sync(0xffffffffu, vv, m);
        dd += __shfl_xor_sync(0xffffffffu, dd, m);
        ad += __shfl_xor_sync(0xffffffffu, ad, m);
    }
    if (lane == 0) {
        float* o = &g_gram[t * 8];
        o[0] = s; o[1] = h; o[2] = vv; o[3] = dd; o[4] = ad;
    }
}

// ---------------- K4: G table  G[t][c] = f_t . mn_c  ----------------
__global__ __launch_bounds__(128) void k_G() {
    __shared__ float4 fsm[128];                 // 8 taps * 64 ch
    const int c = threadIdx.x;
    const bool valid = c < NC;
    float4 m[16];
#pragma unroll
    for (int k = 0; k < 16; k++)
        m[k] = valid ? *(const float4*)&g_mn[c * CH + k * 4]
                     : make_float4(0.f, 0.f, 0.f, 0.f);
    const int base = blockIdx.x * 48;
    for (int g = 0; g < 6; g++) {
        const int t0 = base + g * 8;
        fsm[c] = *(const float4*)&g_featsT[t0 * CH + c * 4];
        __syncthreads();
#pragma unroll
        for (int tt = 0; tt < 8; tt++) {
            const float4* fr = &fsm[tt * 16];
            float acc = 0.f;
#pragma unroll
            for (int k = 0; k < 16; k++) {
                float4 f = fr[k];
                acc += f.x * m[k].x + f.y * m[k].y + f.z * m[k].z + f.w * m[k].w;
            }
            if (valid) g_G[(t0 + tt) * CPAD + c] = acc;
        }
        __syncthreads();
    }
}

// ---------------- K5: per-pixel weight + coefficient scatter ----------------
__global__ __launch_bounds__(512) void k_phaseA(const int* __restrict__ seg) {
    const int i = blockIdx.x * 512 + threadIdx.x;        // exact NPIX coverage
    const int oy = i / OUT_HW, ox = i - oy * OUT_HW;
    const int c = seg[i];
    const float fy = 0.25f * (float)oy - 0.375f;
    const float fx = 0.25f * (float)ox - 0.375f;
    const int by = (int)floorf(fy), bx = (int)floorf(fx);
    int y0, x0; float u, v;
    if (by < 0)              { y0 = 0;         u = 0.f; }
    else if (by >= IN_HW - 1){ y0 = IN_HW - 1; u = 0.f; }
    else                     { y0 = by;        u = fy - (float)by; }
    if (bx < 0)              { x0 = 0;         v = 0.f; }
    else if (bx >= IN_HW - 1){ x0 = IN_HW - 1; v = 0.f; }
    else                     { x0 = bx;        v = fx - (float)bx; }
    const int yp = min(y0 + 1, IN_HW - 1), xp = min(x0 + 1, IN_HW - 1);
    const float wu0 = 1.f - u, wv0 = 1.f - v;
    const float w00 = wu0 * wv0, w01 = wu0 * v, w10 = u * wv0, w11 = u * v;
    const int t00 = y0 * IN_HW + x0, t01 = y0 * IN_HW + xp;
    const int t10 = yp * IN_HW + x0, t11 = yp * IN_HW + xp;

    const float dot = w00 * g_G[t00 * CPAD + c] + w01 * g_G[t01 * CPAD + c]
                    + w10 * g_G[t10 * CPAD + c] + w11 * g_G[t11 * CPAD + c];

    const float4 q00 = *(const float4*)&g_gram[t00 * 8];   // S,H,V,D
    const float ad00 = g_gram[t00 * 8 + 4];
    const float4 q01 = *(const float4*)&g_gram[t01 * 8];   // need S,V
    const float4 q10 = *(const float4*)&g_gram[t10 * 8];   // need S,H
    const float S11  = g_gram[t11 * 8];

    float n2 = w00 * w00 * q00.x + w01 * w01 * q01.x + w10 * w10 * q10.x + w11 * w11 * S11
             + 2.f * (w00 * w01 * q00.y + w10 * w11 * q10.y
                    + w00 * w10 * q00.z + w01 * w11 * q01.z
                    + w00 * w11 * q00.w + w01 * w10 * ad00);
    n2 = fmaxf(n2, 0.f);
    const float s = 1.f - dot / fmaxf(sqrtf(n2), EPSV);

    atomicAdd(&g_A[t00 * CPAD + c], s * w00); atomicAdd(&g_B[t00 * CPAD + c], w00);
    atomicAdd(&g_A[t01 * CPAD + c], s * w01); atomicAdd(&g_B[t01 * CPAD + c], w01);
    atomicAdd(&g_A[t10 * CPAD + c], s * w10); atomicAdd(&g_B[t10 * CPAD + c], w10);
    atomicAdd(&g_A[t11 * CPAD + c], s * w11); atomicAdd(&g_B[t11 * CPAD + c], w11);
}

// ---------------- K6: coefficient GEMM (thread = class, split-K) ----------------
__global__ __launch_bounds__(128) void k_out() {
    __shared__ float  smA[8][CPAD];
    __shared__ float  smB[8][CPAD];
    __shared__ float4 smF[128];                 // 8 taps * 64 ch
    const int c = threadIdx.x;
    const bool valid = c < NC;
    const int zc = valid ? g_iszero[c] : 0;
    float4 acc[16];
#pragma unroll
    for (int k = 0; k < 16; k++) acc[k] = make_float4(0.f, 0.f, 0.f, 0.f);
    float sa = 0.f, sb = 0.f;
    const int base = blockIdx.x * 96;           // 150 * 96 = 14400
    for (int g = 0; g < 12; g++) {
        const int t0 = base + g * 8;
#pragma unroll
        for (int tt = 0; tt < 8; tt++) {
            smA[tt][c] = g_A[(t0 + tt) * CPAD + c];
            smB[tt][c] = g_B[(t0 + tt) * CPAD + c];
        }
        smF[c] = *(const float4*)&g_featsT[t0 * CH + c * 4];
        __syncthreads();
#pragma unroll
        for (int tt = 0; tt < 8; tt++) {
            const float a = smA[tt][c], b = smB[tt][c];
            sa += a; sb += b;
            const float coef = zc ? b : a;
            const float4* fr = &smF[tt * 16];
#pragma unroll
            for (int k = 0; k < 16; k++) {
                float4 f = fr[k];
                acc[k].x += coef * f.x; acc[k].y += coef * f.y;
                acc[k].z += coef * f.z; acc[k].w += coef * f.w;
            }
        }
        __syncthreads();
    }
    if (valid) {
#pragma unroll
        for (int k = 0; k < 16; k++) {
            atomicAdd(&g_acc[c * CH + k * 4 + 0], acc[k].x);
            atomicAdd(&g_acc[c * CH + k * 4 + 1], acc[k].y);
            atomicAdd(&g_acc[c * CH + k * 4 + 2], acc[k].z);
            atomicAdd(&g_acc[c * CH + k * 4 + 3], acc[k].w);
        }
        atomicAdd(&g_sa[c], sa);
        atomicAdd(&g_sb[c], sb);
    }
}

// ---------------- K7: final blend ----------------
__global__ __launch_bounds__(64) void k_blend(const float* __restrict__ memory,
                                              float* __restrict__ out) {
    const int c = blockIdx.x, ch = threadIdx.x;
    const float mem = memory[c * CH + ch];
    const float cnt = g_sb[c];
    float o;
    if (cnt <= 0.5f) {
        o = mem;                                         // class absent
    } else if (g_iszero[c]) {
        o = g_acc[c * CH + ch] / fmaxf(cnt, 1.0f);       // class mean
    } else {
        const float sav = g_sa[c];
        const float denom = (sav != 0.0f) ? sav : 1.0f;
        o = 0.9f * mem + 0.1f * (g_acc[c * CH + ch] / denom);
    }
    out[c * CH + ch] = o;
}

// ---------------- launch ----------------
extern "C" void kernel_launch(void* const* d_in, const int* in_sizes, int n_in,
                              void* d_out, int out_size) {
    const float* feats  = (const float*)d_in[0];   // (1,64,120,120)
    const float* memory = (const float*)d_in[1];   // (124,1,64)
    const int*   seg    = (const int*)d_in[2];     // (1,480,480)
    float* out = (float*)d_out;                    // (124,1,64)

    k_prep<<<NC, 64>>>(memory);
    k_init<<<900, 256>>>(feats);
    k_gram<<<450, 1024>>>();
    k_G<<<300, 128>>>();
    k_phaseA<<<450, 512>>>(seg);
    k_out<<<150, 128>>>();
    k_blend<<<NC, 64>>>(memory, out);
}